// round 12
// baseline (speedup 1.0000x reference)
#include <cuda_runtime.h>

#define NN   128
#define FIN  512
#define EE   128
#define H1D  256
#define H2D  128
#define TPB  512

typedef unsigned long long ull;

__device__ __forceinline__ ull ffma2(ull a, ull b, ull c){
    ull d;
    asm("fma.rn.f32x2 %0, %1, %2, %3;" : "=l"(d) : "l"(a), "l"(b), "l"(c));
    return d;
}
__device__ __forceinline__ ull packff(float x){
    ull d; asm("mov.b64 %0, {%1, %2};" : "=l"(d) : "f"(x), "f"(x)); return d;
}
__device__ __forceinline__ int ld_acquire(const int* p){
    int v;
    asm volatile("ld.acquire.gpu.global.b32 %0, [%1];" : "=r"(v) : "l"(p) : "memory");
    return v;
}
__device__ __forceinline__ void st_relaxed(int* p, int v){
    asm volatile("st.relaxed.gpu.global.b32 [%0], %1;" :: "l"(p), "r"(v) : "memory");
}
__device__ __forceinline__ void red_release_add1(int* p){
    asm volatile("red.release.gpu.global.add.s32 [%0], 1;" :: "l"(p) : "memory");
}

// ---------------- persistent device state ----------------------------------
__device__ float g_P[NN*EE];
__device__ float g_feat0[NN*EE];
__device__ float g_A0[NN*H1D];
__device__ float g_G0[NN*H1D];
__device__ float g_G[NN*H1D];
__device__ float g_feat[NN*EE];
__device__ int   g_cand[NN*4];
__device__ int   g_ccnt[NN];
__device__ int   g_upd[NN];
__device__ int   g_rowcntG[NN];   // G-state dependency counter (decision-time release)
__device__ int   g_rowcntF[NN];   // feat/row-write counter (post-S4b release)
__device__ int   g_isG0[NN];      // 1 iff current G-state of row == G0
__device__ ull   g_touchL[NN], g_touchH[NN];
__device__ int   g_needany[NN];

// ---------------- fused init: one node per block (128 thr) ------------------
__global__ void init_kernel(const float* __restrict__ fo, const float* __restrict__ We,
                            const float* __restrict__ be, const float* __restrict__ adj,
                            const float* __restrict__ W1)
{
    __shared__ float fos[FIN];
    __shared__ float fs[EE];
    __shared__ unsigned bal[4], balc[4];
    const int i = blockIdx.x, e = threadIdx.x;     // 128 threads

    ((float4*)fos)[e] = ((const float4*)(fo + i*FIN))[e];
    unsigned b = __ballot_sync(0xffffffffu, adj[i*NN + e] != 0.0f);
    if ((e & 31) == 0) bal[e >> 5] = b;
    unsigned bc = __ballot_sync(0xffffffffu, (adj[e*NN + i] != 0.0f) || (e == i));
    if ((e & 31) == 0) balc[e >> 5] = bc;
    int fl = (e > i) ? (adj[e*NN + i] != 0.0f) : 0;
    int any = __syncthreads_or(fl);
    if (e == 0) g_needany[i] = any;

    float s = 0.f;
    #pragma unroll 16
    for (int f = 0; f < FIN; f++) s += fos[f] * We[f*EE + e];
    g_P[i*EE+e] = s;
    float f0 = fmaxf(s + be[e], 0.f);
    g_feat0[i*EE+e] = f0;
    g_feat [i*EE+e] = f0;
    fs[e] = f0;

    if (e == 0) {
        g_upd[i]     = 0;
        g_rowcntG[i] = 0;
        g_rowcntF[i] = 0;
        g_isG0[i]    = 1;
        g_touchL[i] = (ull)balc[0] | ((ull)balc[1] << 32);
        g_touchH[i] = (ull)balc[2] | ((ull)balc[3] << 32);
        int c = 0;
        for (int wq = 0; wq < 4; wq++){
            unsigned bb = bal[wq];
            while (bb){
                int bit = __ffs(bb) - 1; bb &= bb - 1;
                int vtx = wq*32 + bit;
                if (c < 4) g_cand[i*4 + c] = vtx;
                c++;
            }
        }
        if (c > 3) c = 3;                          // K=3 -> <=3 distinct
        g_ccnt[i] = c;
    }
    __syncthreads();

    #pragma unroll
    for (int h = 0; h < 2; h++){
        int j = e + h*128;
        float st = 0.f, sb = 0.f;
        #pragma unroll 16
        for (int k = 0; k < EE; k++){
            float f = fs[k];
            st += f * W1[k*H1D + j];
            sb += f * W1[(EE+k)*H1D + j];
        }
        g_A0[i*H1D+j] = st;
        g_G0[i*H1D+j] = sb;
        g_G [i*H1D+j] = sb;
    }
}

// ---------------- S2: NPAIR row-pairs, W2 from smem --------------------------
template<int NPAIR>
__device__ __forceinline__ void s2_compute(const float* __restrict__ h1T,
                                           const float* __restrict__ W2s,
                                           float2* __restrict__ part,
                                           int kslab, int j0)
{
    ull accA[NPAIR], accB[NPAIR];
    #pragma unroll
    for (int p = 0; p < NPAIR; p++){ accA[p] = 0ull; accB[p] = 0ull; }
    #pragma unroll
    for (int kk = 0; kk < 32; kk++){
        int k = kslab*32 + kk;
        float2 wv = *(const float2*)(W2s + k*H2D + j0);
        ull wpa = packff(wv.x), wpb = packff(wv.y);
        if (NPAIR == 2){
            ulonglong2 hp = *(const ulonglong2*)(h1T + 4*k);
            accA[0] = ffma2(hp.x, wpa, accA[0]);
            accB[0] = ffma2(hp.x, wpb, accB[0]);
            accA[1] = ffma2(hp.y, wpa, accA[1]);
            accB[1] = ffma2(hp.y, wpb, accB[1]);
        } else {
            ull hx = *(const ull*)(h1T + 4*k);
            accA[0] = ffma2(hx, wpa, accA[0]);
            accB[0] = ffma2(hx, wpb, accB[0]);
        }
    }
    #pragma unroll
    for (int p = 0; p < NPAIR; p++){
        float2 fa, fb;
        asm("mov.b64 {%0,%1}, %2;" : "=f"(fa.x), "=f"(fa.y) : "l"(accA[p]));
        asm("mov.b64 {%0,%1}, %2;" : "=f"(fb.x), "=f"(fb.y) : "l"(accB[p]));
        part[(p*8 + kslab)*H2D + j0]     = fa;
        part[(p*8 + kslab)*H2D + j0 + 1] = fb;
    }
}

// ---------------- dataflow rollout: 128 CTAs, one node each ------------------
extern __shared__ float smx[];

__global__ void __launch_bounds__(TPB, 1) dataflow_kernel(
    const float* __restrict__ W1, const float* __restrict__ W2,
    const float* __restrict__ b1, const float* __restrict__ b2,
    const float* __restrict__ wlk, const float* __restrict__ blk,
    const float* __restrict__ wact, const float* __restrict__ bact,
    const float* __restrict__ be, float* __restrict__ out)
{
    float* base_ = smx;
    float*  W2s  = base_;  base_ += 32768;
    float*  h1T  = base_;  base_ += 1024;
    float*  partF= base_;  base_ += 4096;
    float*  Grow = base_;  base_ += 768;
    float*  G0s  = base_;  base_ += 768;
    float*  Pvs  = base_;  base_ += 384;
    float*  f0vs = base_;  base_ += 384;
    float*  Pis  = base_;  base_ += 128;
    float*  a_   = base_;  base_ += 256;
    float*  curx = base_;  base_ += 128;
    float*  selP = base_;  base_ += 128;
    float*  b1s  = base_;  base_ += 256;
    float*  b2s  = base_;  base_ += 128;
    float*  wlks = base_;  base_ += 128;
    float*  wa0  = base_;  base_ += 128;
    float*  wa1  = base_;  base_ += 128;
    float*  bes  = base_;  base_ += 128;

    float2* part  = (float2*)partF;
    float*  dual  = partF;
    float*  dualB = partF + 2048;

    __shared__ float s_lk[4], s_a0[4], s_a1[4];
    __shared__ int   s_flagok[3], s_allok;

    const int i    = blockIdx.x;
    const int tid  = threadIdx.x;
    const int w    = tid >> 5;
    const int lane = tid & 31;
    const int kslab = w >> 1, jh = w & 1;
    const int j0 = jh*64 + lane*2;
    const int jg = tid & 63, ks = tid >> 6;

    // ---- pre-wait staging ----
    if (tid < H1D) b1s[tid] = b1[tid];
    if (tid < H2D){ b2s[tid]=b2[tid]; wlks[tid]=wlk[tid];
                    wa0[tid]=wact[2*tid]; wa1[tid]=wact[2*tid+1]; }
    if (tid < EE){ bes[tid] = be[tid]; selP[tid] = 0.f; Pis[tid] = g_P[i*EE+tid]; }
    if (tid < H1D) a_[tid] = g_A0[i*H1D + tid];
    const float blkv = __ldg(blk), ba0v = __ldg(bact), ba1v = __ldg(bact+1);

    #pragma unroll
    for (int q = 0; q < 16; q++)
        ((float4*)W2s)[q*TPB + tid] = ((const float4*)W2)[q*TPB + tid];

    ull w1p[32];
    #pragma unroll
    for (int kk = 0; kk < 16; kk++){
        ulonglong2 t = *(const ulonglong2*)(W1 + (ks*16+kk)*H1D + jg*4);
        w1p[2*kk] = t.x; w1p[2*kk+1] = t.y;
    }

    const int cc = g_ccnt[i];
    int candv[3];
    #pragma unroll
    for (int q = 0; q < 3; q++) candv[q] = (q < cc) ? g_cand[i*4+q] : -1;
    const int needany = g_needany[i];

    ull mskL, mskH;
    if (i < 64){ mskL = (1ull << i) - 1ull; mskH = 0ull; }
    else       { mskL = ~0ull; mskH = (1ull << (i - 64)) - 1ull; }

    const ull tLi = g_touchL[i], tHi = g_touchH[i];
    const int expI = __popcll(tLi & mskL) + __popcll(tHi & mskH);
    const int totI = __popcll(tLi) + __popcll(tHi);
    int selfInCand = 0;
    #pragma unroll
    for (int q = 0; q < 3; q++) if (q < cc && candv[q] == i) selfInCand = 1;

    for (int t = tid; t < 768; t += TPB){
        int q = t >> 8, k = t & 255;
        if (q < cc) G0s[q*256+k] = g_G0[candv[q]*H1D + k];
    }
    if (tid < 384){
        int q = tid >> 7, e = tid & 127;
        if (q < cc){ Pvs[q*128+e] = g_P[candv[q]*EE+e];
                     f0vs[q*128+e] = g_feat0[candv[q]*EE+e]; }
    }
    __syncthreads();   // staging complete (G0s/a_/b1s ready for spec)

    // ---- SPECULATIVE step 0: S1+S2+S3 from static G0s ----
    if (cc > 0){
        int ns0 = cc + 1;
        {
            int k = tid & 255, hi = tid >> 8;
            float ak = a_[k] + b1s[k];
            #pragma unroll
            for (int h = 0; h < 2; h++){
                int s = hi*2 + h; float val = 0.f;
                if (s < ns0){
                    if (s < cc){
                        int v = candv[s];
                        float gg = (v > 0) ? G0s[s*256 + k] : 0.f;  // `if v>0` quirk
                        val = fmaxf(ak + gg, 0.f);
                    } else val = fmaxf(ak, 0.f);                     // sentinel
                }
                h1T[k*4 + s] = val;
            }
        }
        __syncthreads();
        if (ns0 >= 3) s2_compute<2>(h1T, W2s, part, kslab, j0);
        else          s2_compute<1>(h1T, W2s, part, kslab, j0);
        __syncthreads();
        if (w < ns0){
            int pair = w >> 1, el = w & 1;
            float lk = 0.f, p0 = 0.f, p1 = 0.f;
            #pragma unroll
            for (int qq = 0; qq < 4; qq++){
                int j = lane + qq*32;
                float ssm = b2s[j];
                #pragma unroll
                for (int kq = 0; kq < 8; kq++){
                    float2 vv = part[(pair*8 + kq)*H2D + j];
                    ssm += el ? vv.y : vv.x;
                }
                float h = fmaxf(ssm, 0.f);
                lk += h*wlks[j]; p0 += h*wa0[j]; p1 += h*wa1[j];
            }
            #pragma unroll
            for (int off = 16; off; off >>= 1){
                lk += __shfl_xor_sync(0xffffffffu, lk, off);
                p0 += __shfl_xor_sync(0xffffffffu, p0, off);
                p1 += __shfl_xor_sync(0xffffffffu, p1, off);
            }
            if (lane == 0){ s_lk[w]=lk+blkv; s_a0[w]=p0+ba0v; s_a1[w]=p1+ba1v; }
        }
    }

    // ---- wait for candidate rows' G-counters; read flags ----
    int g0mask = 0;
    if (cc > 0){
        if (w == 0){
            int r = -1, ex = 0;
            if (lane < cc){
                r = candv[lane];
                ex = __popcll(g_touchL[r] & mskL) + __popcll(g_touchH[r] & mskH);
            }
            int pend = (r >= 0);
            while (__ballot_sync(0xffffffffu, pend)){
                if (pend && ld_acquire(&g_rowcntG[r]) >= ex) pend = 0;
            }
            int ok = 1;
            if (lane < cc){
                int v = candv[lane];
                ok = (v <= 0) ? 1 : ld_acquire(&g_isG0[v]);
                s_flagok[lane] = ok;
            }
            int all = __all_sync(0xffffffffu, ok);
            if (lane == 0) s_allok = all;
        }
        __syncthreads();

        if (s_allok){
            g0mask = (1 << cc) - 1;         // spec hit: later steps read G0s
        } else {
            // rebuild Grow (mix G0s / g_G) + redo step-0 MLP
            for (int t = tid; t < 768; t += TPB){
                int q = t >> 8, k = t & 255;
                if (q < cc){
                    int v = candv[q];
                    float g = 0.f;
                    if (v > 0) g = s_flagok[q] ? G0s[t] : g_G[v*H1D + k];
                    Grow[t] = g;
                }
            }
            __syncthreads();
            int ns0 = cc + 1;
            {
                int k = tid & 255, hi = tid >> 8;
                float ak = a_[k] + b1s[k];
                #pragma unroll
                for (int h = 0; h < 2; h++){
                    int s = hi*2 + h; float val = 0.f;
                    if (s < ns0){
                        if (s < cc){
                            int v = candv[s];
                            float gg = (v > 0) ? Grow[s*256 + k] : 0.f;
                            val = fmaxf(ak + gg, 0.f);
                        } else val = fmaxf(ak, 0.f);
                    }
                    h1T[k*4 + s] = val;
                }
            }
            __syncthreads();
            if (ns0 >= 3) s2_compute<2>(h1T, W2s, part, kslab, j0);
            else          s2_compute<1>(h1T, W2s, part, kslab, j0);
            __syncthreads();
            if (w < ns0){
                int pair = w >> 1, el = w & 1;
                float lk = 0.f, p0 = 0.f, p1 = 0.f;
                #pragma unroll
                for (int qq = 0; qq < 4; qq++){
                    int j = lane + qq*32;
                    float ssm = b2s[j];
                    #pragma unroll
                    for (int kq = 0; kq < 8; kq++){
                        float2 vv = part[(pair*8 + kq)*H2D + j];
                        ssm += el ? vv.y : vv.x;
                    }
                    float h = fmaxf(ssm, 0.f);
                    lk += h*wlks[j]; p0 += h*wa0[j]; p1 += h*wa1[j];
                }
                #pragma unroll
                for (int off = 16; off; off >>= 1){
                    lk += __shfl_xor_sync(0xffffffffu, lk, off);
                    p0 += __shfl_xor_sync(0xffffffffu, p0, off);
                    p1 += __shfl_xor_sync(0xffffffffu, p1, off);
                }
                if (lane == 0){ s_lk[w]=lk+blkv; s_a0[w]=p0+ba0v; s_a1[w]=p1+ba1v; }
            }
        }
        __syncthreads();
    } else {
        __syncthreads();
    }

    // ---- per-thread uniform rollout state ----
    int aliveM = (1 << cc) - 1, na = cc;
    int done = 0, gdirty = 0, needgi = 0, qi = -1;
    int pub = 0, rowiOK = selfInCand, rowi_g0 = 1;
    float cntf = 0.f;

    for (int step = 0; step < 3; step++){
        if (na == 0) break;

        int slots[4]; int ns = 0;
        #pragma unroll
        for (int q = 0; q < 3; q++) if ((aliveM >> q) & 1) slots[ns++] = q;
        slots[ns++] = -1;                       // sentinel last
        int npair = (ns + 1) >> 1;

        if (step > 0){
            // S1 from G0s / Grow per g0mask
            {
                int k = tid & 255, hi = tid >> 8;
                float ak = a_[k] + b1s[k];
                #pragma unroll
                for (int h = 0; h < 2; h++){
                    int s = hi*2 + h; float val = 0.f;
                    if (s < ns){
                        int q = slots[s];
                        if (q < 0) val = fmaxf(ak, 0.f);
                        else {
                            int v = candv[q];
                            float gg = 0.f;
                            if (v > 0) gg = ((g0mask >> q) & 1) ? G0s[q*256 + k]
                                                                : Grow[q*256 + k];
                            val = fmaxf(ak + gg, 0.f);
                        }
                    }
                    h1T[k*4 + s] = val;
                }
            }
            __syncthreads();
            if (npair == 2) s2_compute<2>(h1T, W2s, part, kslab, j0);
            else            s2_compute<1>(h1T, W2s, part, kslab, j0);
            __syncthreads();
            if (w < ns){
                int pair = w >> 1, el = w & 1;
                float lk = 0.f, p0 = 0.f, p1 = 0.f;
                #pragma unroll
                for (int qq = 0; qq < 4; qq++){
                    int j = lane + qq*32;
                    float ssm = b2s[j];
                    #pragma unroll
                    for (int kq = 0; kq < 8; kq++){
                        float2 vv = part[(pair*8 + kq)*H2D + j];
                        ssm += el ? vv.y : vv.x;
                    }
                    float h = fmaxf(ssm, 0.f);
                    lk += h*wlks[j]; p0 += h*wa0[j]; p1 += h*wa1[j];
                }
                #pragma unroll
                for (int off = 16; off; off >>= 1){
                    lk += __shfl_xor_sync(0xffffffffu, lk, off);
                    p0 += __shfl_xor_sync(0xffffffffu, p0, off);
                    p1 += __shfl_xor_sync(0xffffffffu, p1, off);
                }
                if (lane == 0){ s_lk[w]=lk+blkv; s_a0[w]=p0+ba0v; s_a1[w]=p1+ba1v; }
            }
            __syncthreads();
        }

        // Decision — all threads, uniform registers
        float best = -3.4028235e38f; int bs = -1;
        for (int s = 0; s < ns-1; s++){
            float l = s_lk[s];
            if (l > best){ best = l; bs = s; }
        }
        int vsel = 0, at = 0, qsel = -1, sel = 0; float denom = 1.f;
        if (s_lk[ns-1] > best){
            done = 1;
        } else {
            #pragma unroll
            for (int s = 0; s < 3; s++) if (s == bs) qsel = slots[s];
            vsel = candv[qsel];
            at = (s_a1[bs] > s_a0[bs]) ? 1 : 0;
            denom = cntf + (float)at + 1.0f;
            cntf += (float)at;
            aliveM &= ~(1 << qsel); na--; sel = 1;
            needgi = 0; qi = -1;
            #pragma unroll
            for (int q = 0; q < 3; q++)
                if (((aliveM >> q) & 1) && candv[q] == i){ needgi = 1; qi = q; }
            gdirty = (vsel == i) ? 0 : 1;
        }
        if (done) break;

        // EARLY G-publish: reset-to-G0 has no data; flag then release counter
        if (tid == 0 && vsel != i){
            st_relaxed(&g_isG0[vsel], 1);
            red_release_add1(&g_rowcntG[vsel]);
        }

        // deferred own-row wait: must precede first write to row i
        if (sel && !rowiOK){
            if (w == 0){
                while (ld_acquire(&g_rowcntF[i]) < expI) { }
            }
            __syncthreads();
            rowiOK = 1;
        }

        // S4b: apply updates (all-smem sources; NO g_G reset write)
        {
            if (tid == 0){ g_upd[i] = 1; g_upd[vsel] = 1; }
            int grp = tid >> 7, e = tid & 127;
            if (grp == 0){
                float pv = Pvs[qsel*128+e], pi = Pis[e];
                float nx = fmaxf((selP[e] + (float)at*pv + pi)/denom + bes[e], 0.f);
                float f0v = f0vs[qsel*128+e];
                float fx = (vsel == i) ? f0v : nx;
                if (at) selP[e] += pv;
                g_feat[i*EE + e] = fx;
                curx[e] = fx;
            } else if (grp == 1){
                g_feat[vsel*EE + e] = f0vs[qsel*128+e];
            }
        }
        __syncthreads();
        if (tid == 0 && vsel != i) red_release_add1(&g_rowcntF[vsel]);
        if (vsel != i) pub |= 1 << qsel; else rowi_g0 = 1;

        if (na == 0) break;
        if (step >= 2) break;

        // S5: a = curx @ W1_top (packed regs); + G[i] bottom LDG stream if needgi
        {
            ull acc0 = 0, acc1 = 0;
            #pragma unroll
            for (int kk = 0; kk < 16; kk++){
                ull cp = packff(curx[ks*16 + kk]);
                acc0 = ffma2(w1p[2*kk],   cp, acc0);
                acc1 = ffma2(w1p[2*kk+1], cp, acc1);
            }
            ulonglong2 sb2; sb2.x = 0ull; sb2.y = 0ull;
            if (needgi){
                const float* bwB = W1 + (EE + ks*16)*H1D + jg*4;
                ull b0 = 0, b1u = 0;
                #pragma unroll
                for (int kk = 0; kk < 16; kk++){
                    ulonglong2 wrb = *(const ulonglong2*)(bwB + kk*H1D);
                    ull cp = packff(curx[ks*16 + kk]);
                    b0  = ffma2(wrb.x, cp, b0);
                    b1u = ffma2(wrb.y, cp, b1u);
                }
                sb2.x = b0; sb2.y = b1u;
            }
            ulonglong2 st2; st2.x = acc0; st2.y = acc1;
            *(ulonglong2*)(dual + ks*H1D + jg*4) = st2;
            if (needgi) *(ulonglong2*)(dualB + ks*H1D + jg*4) = sb2;
        }
        __syncthreads();
        if (tid < H1D){
            float ssum = 0.f;
            #pragma unroll
            for (int kq = 0; kq < 8; kq++) ssum += dual[kq*H1D + tid];
            a_[tid] = ssum;
        } else if (needgi){
            int jj = tid - 256;
            float sb = 0.f;
            #pragma unroll
            for (int kq = 0; kq < 8; kq++) sb += dualB[kq*H1D + jj];
            g_G[i*H1D + jj] = sb;
            Grow[qi*256 + jj] = sb;
        }
        if (needgi){ gdirty = 0; rowi_g0 = 0; g0mask &= ~(1 << qi); }
        __syncthreads();
    } // steps

    // ---- termination: publish untouched candidate rows (both counters) ----
    __syncthreads();
    if (tid == 0){
        #pragma unroll
        for (int q = 0; q < 3; q++)
            if (q < cc && !((pub >> q) & 1) && candv[q] != i){
                red_release_add1(&g_rowcntG[candv[q]]);
                red_release_add1(&g_rowcntF[candv[q]]);
            }
    }

    // ---- flush stale G[i] only if some j>i can read it ----
    if (gdirty && needany){
        {
            const float* bwB = W1 + (EE + ks*16)*H1D + jg*4;
            ull b0 = 0, b1u = 0;
            #pragma unroll
            for (int kk = 0; kk < 16; kk++){
                ulonglong2 wrb = *(const ulonglong2*)(bwB + kk*H1D);
                ull cp = packff(curx[ks*16 + kk]);
                b0  = ffma2(wrb.x, cp, b0);
                b1u = ffma2(wrb.y, cp, b1u);
            }
            ulonglong2 st2; st2.x = b0; st2.y = b1u;
            *(ulonglong2*)(dual + ks*H1D + jg*4) = st2;
        }
        __syncthreads();
        if (tid < H1D){
            float ssum = 0.f;
            #pragma unroll
            for (int kq = 0; kq < 8; kq++) ssum += dual[kq*H1D + tid];
            g_G[i*H1D + tid] = ssum;
        }
        rowi_g0 = 0;
    }
    __syncthreads();
    if (tid == 0){
        st_relaxed(&g_isG0[i], rowi_g0);
        red_release_add1(&g_rowcntG[i]);   // own G-state final
        red_release_add1(&g_rowcntF[i]);   // own row final
    }

    // ---- out phase: wait until every toucher of row i finalized feat ----
    if (w == 0){
        while (ld_acquire(&g_rowcntF[i]) < totI) { }
    }
    __syncthreads();
    if (tid < EE){
        int u  = __ldcg(&g_upd[i]);
        float f = __ldcg(&g_feat[i*EE + tid]);
        out[i*EE + tid] = u ? f : 0.f;
    }
}

// ---------------- launch ------------------------------------------------------
static const int DYN_SMEM = (32768 + 1024 + 4096 + 768 + 768 + 384 + 384
                             + 128 + 256 + 128 + 128 + 256 + 128 + 128
                             + 128 + 128 + 128) * (int)sizeof(float);

extern "C" void kernel_launch(void* const* d_in, const int* in_sizes, int n_in,
                              void* d_out, int out_size)
{
    const float* adj = (const float*)d_in[0];
    const float* fo  = (const float*)d_in[1];
    // d_in[2] = labels (unused)
    const float* We  = (const float*)d_in[3];
    const float* be  = (const float*)d_in[4];
    const float* W1  = (const float*)d_in[5];
    const float* b1  = (const float*)d_in[6];
    const float* W2  = (const float*)d_in[7];
    const float* b2  = (const float*)d_in[8];
    const float* wlk = (const float*)d_in[9];
    const float* blk = (const float*)d_in[10];
    const float* wac = (const float*)d_in[11];
    const float* bac = (const float*)d_in[12];
    float* out = (float*)d_out;

    cudaFuncSetAttribute(dataflow_kernel, cudaFuncAttributeMaxDynamicSharedMemorySize, DYN_SMEM);

    init_kernel<<<NN, 128>>>(fo, We, be, adj, W1);
    dataflow_kernel<<<NN, TPB, DYN_SMEM>>>(W1, W2, b1, b2, wlk, blk, wac, bac, be, out);
}

// round 13
// speedup vs baseline: 1.0962x; 1.0962x over previous
#include <cuda_runtime.h>

#define NN   128
#define FIN  512
#define EE   128
#define H1D  256
#define H2D  128
#define TPB  512

typedef unsigned long long ull;

__device__ __forceinline__ ull ffma2(ull a, ull b, ull c){
    ull d;
    asm("fma.rn.f32x2 %0, %1, %2, %3;" : "=l"(d) : "l"(a), "l"(b), "l"(c));
    return d;
}
__device__ __forceinline__ ull packff(float x){
    ull d; asm("mov.b64 %0, {%1, %2};" : "=l"(d) : "f"(x), "f"(x)); return d;
}
__device__ __forceinline__ int ld_acquire(const int* p){
    int v;
    asm volatile("ld.acquire.gpu.global.b32 %0, [%1];" : "=r"(v) : "l"(p) : "memory");
    return v;
}
__device__ __forceinline__ void red_release_add1(int* p){
    asm volatile("red.release.gpu.global.add.s32 [%0], 1;" :: "l"(p) : "memory");
}

// ---------------- persistent device state ----------------------------------
__device__ float g_P[NN*EE];
__device__ float g_feat0[NN*EE];
__device__ float g_G0[NN*H1D];
__device__ float g_G[NN*H1D];
__device__ float g_feat[NN*EE];
__device__ int   g_upd[NN];
__device__ int   g_rowcnt[NN];    // per-row finalization counter
__device__ int   g_isG0[NN];      // 1 iff g_G[row] == G0[row]
__device__ ull   g_touchL[NN], g_touchH[NN];
__device__ int   g_init[NN];      // per-node init-done counter

// ---------------- zero: reset counters for this launch ----------------------
__global__ void zero_kernel(){
    int t = threadIdx.x;            // 128 threads
    g_rowcnt[t] = 0;
    g_upd[t]    = 0;
    g_isG0[t]   = 1;
    g_init[t]   = 0;
}

// ---------------- S2: NPAIR row-pairs, W2 from smem --------------------------
template<int NPAIR>
__device__ __forceinline__ void s2_compute(const float* __restrict__ h1T,
                                           const float* __restrict__ W2s,
                                           float2* __restrict__ part,
                                           int kslab, int j0)
{
    ull accA[NPAIR], accB[NPAIR];
    #pragma unroll
    for (int p = 0; p < NPAIR; p++){ accA[p] = 0ull; accB[p] = 0ull; }
    #pragma unroll
    for (int kk = 0; kk < 32; kk++){
        int k = kslab*32 + kk;
        float2 wv = *(const float2*)(W2s + k*H2D + j0);
        ull wpa = packff(wv.x), wpb = packff(wv.y);
        if (NPAIR == 2){
            ulonglong2 hp = *(const ulonglong2*)(h1T + 4*k);
            accA[0] = ffma2(hp.x, wpa, accA[0]);
            accB[0] = ffma2(hp.x, wpb, accB[0]);
            accA[1] = ffma2(hp.y, wpa, accA[1]);
            accB[1] = ffma2(hp.y, wpb, accB[1]);
        } else {
            ull hx = *(const ull*)(h1T + 4*k);
            accA[0] = ffma2(hx, wpa, accA[0]);
            accB[0] = ffma2(hx, wpb, accB[0]);
        }
    }
    #pragma unroll
    for (int p = 0; p < NPAIR; p++){
        float2 fa, fb;
        asm("mov.b64 {%0,%1}, %2;" : "=f"(fa.x), "=f"(fa.y) : "l"(accA[p]));
        asm("mov.b64 {%0,%1}, %2;" : "=f"(fb.x), "=f"(fb.y) : "l"(accB[p]));
        part[(p*8 + kslab)*H2D + j0]     = fa;
        part[(p*8 + kslab)*H2D + j0 + 1] = fb;
    }
}

// ---------------- dataflow rollout + fused init: 128 CTAs -------------------
extern __shared__ float smx[];

__global__ void __launch_bounds__(TPB, 1) dataflow_kernel(
    const float* __restrict__ adj, const float* __restrict__ fo,
    const float* __restrict__ We,  const float* __restrict__ be,
    const float* __restrict__ W1, const float* __restrict__ W2,
    const float* __restrict__ b1, const float* __restrict__ b2,
    const float* __restrict__ wlk, const float* __restrict__ blk,
    const float* __restrict__ wact, const float* __restrict__ bact,
    float* __restrict__ out)
{
    float* base_ = smx;
    float*  W2s  = base_;  base_ += 32768;
    float*  h1T  = base_;  base_ += 1024;
    float*  partF= base_;  base_ += 4096;
    float*  Grow = base_;  base_ += 768;
    float*  G0s  = base_;  base_ += 768;
    float*  Pvs  = base_;  base_ += 384;
    float*  f0vs = base_;  base_ += 384;
    float*  Pis  = base_;  base_ += 128;
    float*  a_   = base_;  base_ += 256;
    float*  curx = base_;  base_ += 128;
    float*  selP = base_;  base_ += 128;
    float*  b1s  = base_;  base_ += 256;
    float*  b2s  = base_;  base_ += 128;
    float*  wlks = base_;  base_ += 128;
    float*  wa0  = base_;  base_ += 128;
    float*  wa1  = base_;  base_ += 128;
    float*  bes  = base_;  base_ += 128;

    float2* part  = (float2*)partF;
    float*  dual  = partF;
    float*  dualB = partF + 2048;
    float*  fos   = partF;             // init staging aliases partF (512 floats)

    __shared__ float s_lk[4], s_a0[4], s_a1[4];
    __shared__ int   s_flagok[3], s_allok;
    __shared__ unsigned s_bal[4], s_balc[4];

    const int i    = blockIdx.x;
    const int tid  = threadIdx.x;
    const int w    = tid >> 5;
    const int lane = tid & 31;
    const int kslab = w >> 1, jh = w & 1;
    const int j0 = jh*64 + lane*2;
    const int jg = tid & 63, ks = tid >> 6;

    // ---- staging: constants, W2->smem, W1_top->regs ----
    if (tid < H1D) b1s[tid] = b1[tid];
    if (tid < H2D){ b2s[tid]=b2[tid]; wlks[tid]=wlk[tid];
                    wa0[tid]=wact[2*tid]; wa1[tid]=wact[2*tid+1]; }
    if (tid < EE){ bes[tid] = be[tid]; selP[tid] = 0.f; }
    const float blkv = __ldg(blk), ba0v = __ldg(bact), ba1v = __ldg(bact+1);

    #pragma unroll
    for (int q = 0; q < 16; q++)
        ((float4*)W2s)[q*TPB + tid] = ((const float4*)W2)[q*TPB + tid];

    ull w1p[32];
    #pragma unroll
    for (int kk = 0; kk < 16; kk++){
        ulonglong2 t = *(const ulonglong2*)(W1 + (ks*16+kk)*H1D + jg*4);
        w1p[2*kk] = t.x; w1p[2*kk+1] = t.y;
    }

    // ---- fused init phase A (dependency-free) ----
    fos[tid] = fo[i*FIN + tid];
    if (tid < 128){
        int e = tid;
        unsigned b  = __ballot_sync(0xffffffffu, adj[i*NN + e] != 0.0f);
        unsigned bc = __ballot_sync(0xffffffffu, (adj[e*NN + i] != 0.0f) || (e == i));
        if ((e & 31) == 0){ s_bal[e >> 5] = b; s_balc[e >> 5] = bc; }
    }
    __syncthreads();

    // uniform: touch masks, candidates, needany (every thread, registers)
    const ull tLi = (ull)s_balc[0] | ((ull)s_balc[1] << 32);
    const ull tHi = (ull)s_balc[2] | ((ull)s_balc[3] << 32);
    int cc = 0; int candv[3] = {-1,-1,-1};
    {
        int c = 0;
        #pragma unroll
        for (int wq = 0; wq < 4; wq++){
            unsigned bb = s_bal[wq];
            while (bb){
                int bit = __ffs(bb) - 1; bb &= bb - 1;
                int vtx = wq*32 + bit;
                if (c < 3) candv[c] = vtx;
                c++;
            }
        }
        cc = (c > 3) ? 3 : c;                   // K=3 -> <=3 distinct
    }
    int needany;
    {
        ull aL, aH;
        if (i < 63)       { aL = tLi & ~((2ull << i) - 1ull); aH = tHi; }
        else if (i == 63) { aL = 0ull; aH = tHi; }
        else if (i < 127) { aL = 0ull; aH = tHi & ~((2ull << (i-64)) - 1ull); }
        else              { aL = 0ull; aH = 0ull; }
        needany = ((aL | aH) != 0ull);
    }
    ull mskL, mskH;
    if (i < 64){ mskL = (1ull << i) - 1ull; mskH = 0ull; }
    else       { mskL = ~0ull; mskH = (1ull << (i - 64)) - 1ull; }
    const int expI = __popcll(tLi & mskL) + __popcll(tHi & mskH);
    const int totI = __popcll(tLi) + __popcll(tHi);
    int selfInCand = 0;
    #pragma unroll
    for (int q = 0; q < 3; q++) if (q < cc && candv[q] == i) selfInCand = 1;

    // P / feat0 (exact per-output f order)
    if (tid < 128){
        int e = tid;
        float s = 0.f;
        #pragma unroll 16
        for (int f = 0; f < FIN; f++) s += fos[f] * We[f*EE + e];
        g_P[i*EE + e] = s;
        Pis[e] = s;
        float f0 = fmaxf(s + bes[e], 0.f);
        g_feat0[i*EE + e] = f0;
        curx[e] = f0;                   // fs staging for A0/G0
    }
    __syncthreads();

    // A0 (smem-only) / G0 / G (exact per-output k order)
    if (tid < H1D){
        int j = tid;
        float st = 0.f, sb = 0.f;
        #pragma unroll 16
        for (int k = 0; k < EE; k++){
            float f = curx[k];
            st += f * W1[k*H1D + j];
            sb += f * W1[(EE+k)*H1D + j];
        }
        a_[j] = st;
        g_G0[i*H1D + j] = sb;
        g_G [i*H1D + j] = sb;
    }
    if (tid == 0){ g_touchL[i] = tLi; g_touchH[i] = tHi; }
    __syncthreads();
    if (tid == 0) red_release_add1(&g_init[i]);   // publish init (cumulative)

    // ---- phase B: wait candidates' init, then prefetch their static rows ----
    if (cc > 0){
        if (w == 0){
            int r = (lane < cc) ? candv[lane] : -1;
            int pend = (r >= 0);
            while (__ballot_sync(0xffffffffu, pend)){
                if (pend && ld_acquire(&g_init[r]) >= 1) pend = 0;
            }
        }
        __syncthreads();
    } else {
        __syncthreads();
    }

    for (int t = tid; t < 768; t += TPB){
        int q = t >> 8, k = t & 255;
        if (q < cc) G0s[q*256+k] = g_G0[candv[q]*H1D + k];
    }
    if (tid < 384){
        int q = tid >> 7, e = tid & 127;
        if (q < cc){ Pvs[q*128+e] = g_P[candv[q]*EE+e];
                     f0vs[q*128+e] = g_feat0[candv[q]*EE+e]; }
    }
    __syncthreads();   // staging complete (G0s/a_/b1s ready for spec)

    // ---- SPECULATIVE step 0: S1+S2+S3 from static G0s ----
    if (cc > 0){
        int ns0 = cc + 1;
        {
            int k = tid & 255, hi = tid >> 8;
            float ak = a_[k] + b1s[k];
            #pragma unroll
            for (int h = 0; h < 2; h++){
                int s = hi*2 + h; float val = 0.f;
                if (s < ns0){
                    if (s < cc){
                        int v = candv[s];
                        float gg = (v > 0) ? G0s[s*256 + k] : 0.f;  // `if v>0` quirk
                        val = fmaxf(ak + gg, 0.f);
                    } else val = fmaxf(ak, 0.f);                     // sentinel
                }
                h1T[k*4 + s] = val;
            }
        }
        __syncthreads();
        if (ns0 >= 3) s2_compute<2>(h1T, W2s, part, kslab, j0);
        else          s2_compute<1>(h1T, W2s, part, kslab, j0);
        __syncthreads();
        if (w < ns0){
            int pair = w >> 1, el = w & 1;
            float lk = 0.f, p0 = 0.f, p1 = 0.f;
            #pragma unroll
            for (int qq = 0; qq < 4; qq++){
                int j = lane + qq*32;
                float ssm = b2s[j];
                #pragma unroll
                for (int kq = 0; kq < 8; kq++){
                    float2 vv = part[(pair*8 + kq)*H2D + j];
                    ssm += el ? vv.y : vv.x;
                }
                float h = fmaxf(ssm, 0.f);
                lk += h*wlks[j]; p0 += h*wa0[j]; p1 += h*wa1[j];
            }
            #pragma unroll
            for (int off = 16; off; off >>= 1){
                lk += __shfl_xor_sync(0xffffffffu, lk, off);
                p0 += __shfl_xor_sync(0xffffffffu, p0, off);
                p1 += __shfl_xor_sync(0xffffffffu, p1, off);
            }
            if (lane == 0){ s_lk[w]=lk+blkv; s_a0[w]=p0+ba0v; s_a1[w]=p1+ba1v; }
        }
    }

    // ---- wait for candidate rows to reach their prefix counts ----
    if (cc > 0){
        if (w == 0){
            int r = -1, ex = 0;
            if (lane < cc){
                r = candv[lane];
                ex = __popcll(g_touchL[r] & mskL) + __popcll(g_touchH[r] & mskH);
            }
            int pend = (r >= 0);
            while (__ballot_sync(0xffffffffu, pend)){
                if (pend && ld_acquire(&g_rowcnt[r]) >= ex) pend = 0;
            }
            int ok = 1;
            if (lane < cc){
                int v = candv[lane];
                ok = (v <= 0) ? 1 : ld_acquire(&g_isG0[v]);
                s_flagok[lane] = ok;
            }
            int all = __all_sync(0xffffffffu, ok);
            if (lane == 0) s_allok = all;
        }
        __syncthreads();

        if (s_allok){
            // spec hit: s_lk/s_a0/s_a1 valid; Grow = G0s for later steps
            for (int t = tid; t < 768; t += TPB){
                int q = t >> 8;
                if (q < cc) Grow[t] = G0s[t];
            }
        } else {
            // rebuild: Grow from g_G (flag 0) / G0s (flag 1), redo step-0 MLP
            for (int t = tid; t < 768; t += TPB){
                int q = t >> 8, k = t & 255;
                if (q < cc){
                    int v = candv[q];
                    float g = 0.f;
                    if (v > 0) g = s_flagok[q] ? G0s[t] : g_G[v*H1D + k];
                    Grow[t] = g;
                }
            }
            __syncthreads();
            int ns0 = cc + 1;
            {
                int k = tid & 255, hi = tid >> 8;
                float ak = a_[k] + b1s[k];
                #pragma unroll
                for (int h = 0; h < 2; h++){
                    int s = hi*2 + h; float val = 0.f;
                    if (s < ns0){
                        if (s < cc){
                            int v = candv[s];
                            float gg = (v > 0) ? Grow[s*256 + k] : 0.f;
                            val = fmaxf(ak + gg, 0.f);
                        } else val = fmaxf(ak, 0.f);
                    }
                    h1T[k*4 + s] = val;
                }
            }
            __syncthreads();
            if (ns0 >= 3) s2_compute<2>(h1T, W2s, part, kslab, j0);
            else          s2_compute<1>(h1T, W2s, part, kslab, j0);
            __syncthreads();
            if (w < ns0){
                int pair = w >> 1, el = w & 1;
                float lk = 0.f, p0 = 0.f, p1 = 0.f;
                #pragma unroll
                for (int qq = 0; qq < 4; qq++){
                    int j = lane + qq*32;
                    float ssm = b2s[j];
                    #pragma unroll
                    for (int kq = 0; kq < 8; kq++){
                        float2 vv = part[(pair*8 + kq)*H2D + j];
                        ssm += el ? vv.y : vv.x;
                    }
                    float h = fmaxf(ssm, 0.f);
                    lk += h*wlks[j]; p0 += h*wa0[j]; p1 += h*wa1[j];
                }
                #pragma unroll
                for (int off = 16; off; off >>= 1){
                    lk += __shfl_xor_sync(0xffffffffu, lk, off);
                    p0 += __shfl_xor_sync(0xffffffffu, p0, off);
                    p1 += __shfl_xor_sync(0xffffffffu, p1, off);
                }
                if (lane == 0){ s_lk[w]=lk+blkv; s_a0[w]=p0+ba0v; s_a1[w]=p1+ba1v; }
            }
        }
        __syncthreads();
    } else {
        __syncthreads();
    }

    // ---- per-thread uniform rollout state ----
    int aliveM = (1 << cc) - 1, na = cc;
    int done = 0, gdirty = 0, needgi = 0, qi = -1;
    int pub = 0, rowiOK = selfInCand, rowi_g0 = 1;
    float cntf = 0.f;

    for (int step = 0; step < 3; step++){
        if (na == 0) break;

        int slots[4]; int ns = 0;
        #pragma unroll
        for (int q = 0; q < 3; q++) if ((aliveM >> q) & 1) slots[ns++] = q;
        slots[ns++] = -1;                       // sentinel last
        int npair = (ns + 1) >> 1;

        if (step > 0){
            // S1 from Grow
            {
                int k = tid & 255, hi = tid >> 8;
                float ak = a_[k] + b1s[k];
                #pragma unroll
                for (int h = 0; h < 2; h++){
                    int s = hi*2 + h; float val = 0.f;
                    if (s < ns){
                        int q = slots[s];
                        if (q < 0) val = fmaxf(ak, 0.f);
                        else {
                            int v = candv[q];
                            float gg = (v > 0) ? Grow[q*256 + k] : 0.f;
                            val = fmaxf(ak + gg, 0.f);
                        }
                    }
                    h1T[k*4 + s] = val;
                }
            }
            __syncthreads();
            if (npair == 2) s2_compute<2>(h1T, W2s, part, kslab, j0);
            else            s2_compute<1>(h1T, W2s, part, kslab, j0);
            __syncthreads();
            if (w < ns){
                int pair = w >> 1, el = w & 1;
                float lk = 0.f, p0 = 0.f, p1 = 0.f;
                #pragma unroll
                for (int qq = 0; qq < 4; qq++){
                    int j = lane + qq*32;
                    float ssm = b2s[j];
                    #pragma unroll
                    for (int kq = 0; kq < 8; kq++){
                        float2 vv = part[(pair*8 + kq)*H2D + j];
                        ssm += el ? vv.y : vv.x;
                    }
                    float h = fmaxf(ssm, 0.f);
                    lk += h*wlks[j]; p0 += h*wa0[j]; p1 += h*wa1[j];
                }
                #pragma unroll
                for (int off = 16; off; off >>= 1){
                    lk += __shfl_xor_sync(0xffffffffu, lk, off);
                    p0 += __shfl_xor_sync(0xffffffffu, p0, off);
                    p1 += __shfl_xor_sync(0xffffffffu, p1, off);
                }
                if (lane == 0){ s_lk[w]=lk+blkv; s_a0[w]=p0+ba0v; s_a1[w]=p1+ba1v; }
            }
            __syncthreads();
        }

        // Decision — all threads, uniform registers
        float best = -3.4028235e38f; int bs = -1;
        for (int s = 0; s < ns-1; s++){
            float l = s_lk[s];
            if (l > best){ best = l; bs = s; }
        }
        int vsel = 0, at = 0, qsel = -1, sel = 0; float denom = 1.f;
        if (s_lk[ns-1] > best){
            done = 1;
        } else {
            #pragma unroll
            for (int s = 0; s < 3; s++) if (s == bs) qsel = slots[s];
            vsel = candv[qsel];
            at = (s_a1[bs] > s_a0[bs]) ? 1 : 0;
            denom = cntf + (float)at + 1.0f;
            cntf += (float)at;
            aliveM &= ~(1 << qsel); na--; sel = 1;
            needgi = 0; qi = -1;
            #pragma unroll
            for (int q = 0; q < 3; q++)
                if (((aliveM >> q) & 1) && candv[q] == i){ needgi = 1; qi = q; }
            gdirty = (vsel == i) ? 0 : 1;
        }
        if (done) break;

        // deferred own-row wait: must precede first write to row i
        if (sel && !rowiOK){
            if (w == 0){
                while (ld_acquire(&g_rowcnt[i]) < expI) { }
            }
            __syncthreads();
            rowiOK = 1;
        }

        // S4b: apply updates (all-smem sources)
        {
            if (tid == 0){
                g_upd[i] = 1; g_upd[vsel] = 1;
                if (vsel != i) g_isG0[vsel] = 1;     // reset -> G0
            }
            int grp = tid >> 7, e = tid & 127;
            if (grp == 0){
                float pv = Pvs[qsel*128+e], pi = Pis[e];
                float nx = fmaxf((selP[e] + (float)at*pv + pi)/denom + bes[e], 0.f);
                float f0v = f0vs[qsel*128+e];
                float fx = (vsel == i) ? f0v : nx;
                if (at) selP[e] += pv;
                g_feat[i*EE + e] = fx;
                curx[e] = fx;
            } else if (grp == 1){
                g_feat[vsel*EE + e] = f0vs[qsel*128+e];
            } else {
                int jj = tid - 256;
                g_G[vsel*H1D + jj] = G0s[qsel*256 + jj];
            }
        }
        __syncthreads();                               // cumulative release below
        if (tid == 0 && vsel != i) red_release_add1(&g_rowcnt[vsel]);
        if (vsel != i) pub |= 1 << qsel; else rowi_g0 = 1;

        if (na == 0) break;
        if (step >= 2) break;

        // S5: a = curx @ W1_top (packed regs); + G[i] bottom LDG stream if needgi
        {
            ull acc0 = 0, acc1 = 0;
            #pragma unroll
            for (int kk = 0; kk < 16; kk++){
                ull cp = packff(curx[ks*16 + kk]);
                acc0 = ffma2(w1p[2*kk],   cp, acc0);
                acc1 = ffma2(w1p[2*kk+1], cp, acc1);
            }
            ulonglong2 sb2; sb2.x = 0ull; sb2.y = 0ull;
            if (needgi){
                const float* bwB = W1 + (EE + ks*16)*H1D + jg*4;
                ull b0 = 0, b1u = 0;
                #pragma unroll
                for (int kk = 0; kk < 16; kk++){
                    ulonglong2 wrb = *(const ulonglong2*)(bwB + kk*H1D);
                    ull cp = packff(curx[ks*16 + kk]);
                    b0  = ffma2(wrb.x, cp, b0);
                    b1u = ffma2(wrb.y, cp, b1u);
                }
                sb2.x = b0; sb2.y = b1u;
            }
            ulonglong2 st2; st2.x = acc0; st2.y = acc1;
            *(ulonglong2*)(dual + ks*H1D + jg*4) = st2;
            if (needgi) *(ulonglong2*)(dualB + ks*H1D + jg*4) = sb2;
        }
        __syncthreads();
        if (tid < H1D){
            float ssum = 0.f;
            #pragma unroll
            for (int kq = 0; kq < 8; kq++) ssum += dual[kq*H1D + tid];
            a_[tid] = ssum;
        } else if (needgi){
            int jj = tid - 256;
            float sb = 0.f;
            #pragma unroll
            for (int kq = 0; kq < 8; kq++) sb += dualB[kq*H1D + jj];
            g_G[i*H1D + jj] = sb;
            Grow[qi*256 + jj] = sb;
        }
        if (needgi){ gdirty = 0; rowi_g0 = 0; }
        __syncthreads();
    } // steps

    // ---- termination: publish untouched candidate rows ----
    __syncthreads();
    if (tid == 0){
        #pragma unroll
        for (int q = 0; q < 3; q++)
            if (q < cc && !((pub >> q) & 1) && candv[q] != i)
                red_release_add1(&g_rowcnt[candv[q]]);
    }

    // ---- flush stale G[i] only if some j>i can read it ----
    if (gdirty && needany){
        {
            const float* bwB = W1 + (EE + ks*16)*H1D + jg*4;
            ull b0 = 0, b1u = 0;
            #pragma unroll
            for (int kk = 0; kk < 16; kk++){
                ulonglong2 wrb = *(const ulonglong2*)(bwB + kk*H1D);
                ull cp = packff(curx[ks*16 + kk]);
                b0  = ffma2(wrb.x, cp, b0);
                b1u = ffma2(wrb.y, cp, b1u);
            }
            ulonglong2 st2; st2.x = b0; st2.y = b1u;
            *(ulonglong2*)(dual + ks*H1D + jg*4) = st2;
        }
        __syncthreads();
        if (tid < H1D){
            float ssum = 0.f;
            #pragma unroll
            for (int kq = 0; kq < 8; kq++) ssum += dual[kq*H1D + tid];
            g_G[i*H1D + tid] = ssum;
        }
        rowi_g0 = 0;
    }
    __syncthreads();
    if (tid == 0){
        g_isG0[i] = rowi_g0;
        red_release_add1(&g_rowcnt[i]);   // own row final
    }

    // ---- out phase: wait until every toucher of row i has finalized ----
    if (w == 0){
        while (ld_acquire(&g_rowcnt[i]) < totI) { }
    }
    __syncthreads();
    if (tid < EE){
        int u  = __ldcg(&g_upd[i]);
        float f = __ldcg(&g_feat[i*EE + tid]);
        out[i*EE + tid] = u ? f : 0.f;
    }
}

// ---------------- launch ------------------------------------------------------
static const int DYN_SMEM = (32768 + 1024 + 4096 + 768 + 768 + 384 + 384
                             + 128 + 256 + 128 + 128 + 256 + 128 + 128
                             + 128 + 128 + 128) * (int)sizeof(float);

extern "C" void kernel_launch(void* const* d_in, const int* in_sizes, int n_in,
                              void* d_out, int out_size)
{
    const float* adj = (const float*)d_in[0];
    const float* fo  = (const float*)d_in[1];
    // d_in[2] = labels (unused)
    const float* We  = (const float*)d_in[3];
    const float* be  = (const float*)d_in[4];
    const float* W1  = (const float*)d_in[5];
    const float* b1  = (const float*)d_in[6];
    const float* W2  = (const float*)d_in[7];
    const float* b2  = (const float*)d_in[8];
    const float* wlk = (const float*)d_in[9];
    const float* blk = (const float*)d_in[10];
    const float* wac = (const float*)d_in[11];
    const float* bac = (const float*)d_in[12];
    float* out = (float*)d_out;

    cudaFuncSetAttribute(dataflow_kernel, cudaFuncAttributeMaxDynamicSharedMemorySize, DYN_SMEM);

    zero_kernel<<<1, 128>>>();
    dataflow_kernel<<<NN, TPB, DYN_SMEM>>>(adj, fo, We, be, W1, W2,
                                           b1, b2, wlk, blk, wac, bac, out);
}

// round 14
// speedup vs baseline: 1.2583x; 1.1478x over previous
#include <cuda_runtime.h>

#define NN   128
#define FIN  512
#define EE   128
#define H1D  256
#define H2D  128
#define TPB  512

typedef unsigned long long ull;

__device__ __forceinline__ ull ffma2(ull a, ull b, ull c){
    ull d;
    asm("fma.rn.f32x2 %0, %1, %2, %3;" : "=l"(d) : "l"(a), "l"(b), "l"(c));
    return d;
}
__device__ __forceinline__ ull packff(float x){
    ull d; asm("mov.b64 %0, {%1, %2};" : "=l"(d) : "f"(x), "f"(x)); return d;
}
__device__ __forceinline__ int ld_acquire(const int* p){
    int v;
    asm volatile("ld.acquire.gpu.global.b32 %0, [%1];" : "=r"(v) : "l"(p) : "memory");
    return v;
}
__device__ __forceinline__ void red_release_add1(int* p){
    asm volatile("red.release.gpu.global.add.s32 [%0], 1;" :: "l"(p) : "memory");
}

// ---------------- persistent device state ----------------------------------
__device__ float g_P[NN*EE];
__device__ float g_feat0[NN*EE];
__device__ float g_G0[NN*H1D];
__device__ float g_G[NN*H1D];
__device__ float g_feat[NN*EE];
__device__ int   g_upd[NN];
__device__ int   g_rowcnt[NN];
__device__ int   g_isG0[NN];
__device__ ull   g_touchL[NN], g_touchH[NN];
__device__ int   g_init[NN];

// ---------------- zero: reset counters for this launch ----------------------
__global__ void zero_kernel(){
    int t = threadIdx.x;
    g_rowcnt[t] = 0;
    g_upd[t]    = 0;
    g_isG0[t]   = 1;
    g_init[t]   = 0;
}

// ---------------- S2: NPAIR row-pairs, W2 from smem --------------------------
template<int NPAIR>
__device__ __forceinline__ void s2_compute(const float* __restrict__ h1T,
                                           const float* __restrict__ W2s,
                                           float2* __restrict__ part,
                                           int kslab, int j0)
{
    ull accA[NPAIR], accB[NPAIR];
    #pragma unroll
    for (int p = 0; p < NPAIR; p++){ accA[p] = 0ull; accB[p] = 0ull; }
    #pragma unroll
    for (int kk = 0; kk < 32; kk++){
        int k = kslab*32 + kk;
        float2 wv = *(const float2*)(W2s + k*H2D + j0);
        ull wpa = packff(wv.x), wpb = packff(wv.y);
        if (NPAIR == 2){
            ulonglong2 hp = *(const ulonglong2*)(h1T + 4*k);
            accA[0] = ffma2(hp.x, wpa, accA[0]);
            accB[0] = ffma2(hp.x, wpb, accB[0]);
            accA[1] = ffma2(hp.y, wpa, accA[1]);
            accB[1] = ffma2(hp.y, wpb, accB[1]);
        } else {
            ull hx = *(const ull*)(h1T + 4*k);
            accA[0] = ffma2(hx, wpa, accA[0]);
            accB[0] = ffma2(hx, wpb, accB[0]);
        }
    }
    #pragma unroll
    for (int p = 0; p < NPAIR; p++){
        float2 fa, fb;
        asm("mov.b64 {%0,%1}, %2;" : "=f"(fa.x), "=f"(fa.y) : "l"(accA[p]));
        asm("mov.b64 {%0,%1}, %2;" : "=f"(fb.x), "=f"(fb.y) : "l"(accB[p]));
        part[(p*8 + kslab)*H2D + j0]     = fa;
        part[(p*8 + kslab)*H2D + j0 + 1] = fb;
    }
}

// ---------------- dataflow rollout + fused init + full-node spec -------------
extern __shared__ float smx[];

__global__ void __launch_bounds__(TPB, 1) dataflow_kernel(
    const float* __restrict__ adj, const float* __restrict__ fo,
    const float* __restrict__ We,  const float* __restrict__ be,
    const float* __restrict__ W1, const float* __restrict__ W2,
    const float* __restrict__ b1, const float* __restrict__ b2,
    const float* __restrict__ wlk, const float* __restrict__ blk,
    const float* __restrict__ wact, const float* __restrict__ bact,
    float* __restrict__ out)
{
    float* base_ = smx;
    float*  W2s  = base_;  base_ += 32768;
    float*  h1T  = base_;  base_ += 1024;
    float*  partF= base_;  base_ += 4096;
    float*  Grow = base_;  base_ += 768;
    float*  G0s  = base_;  base_ += 768;
    float*  Pvs  = base_;  base_ += 384;
    float*  f0vs = base_;  base_ += 384;
    float*  Pis  = base_;  base_ += 128;
    float*  a_   = base_;  base_ += 256;
    float*  a0s  = base_;  base_ += 256;   // A0[i] copy (for miss re-run)
    float*  Gis  = base_;  base_ += 256;   // custom G[i] value (spec)
    float*  curx = base_;  base_ += 128;
    float*  selP = base_;  base_ += 128;
    float*  b1s  = base_;  base_ += 256;
    float*  b2s  = base_;  base_ += 128;
    float*  wlks = base_;  base_ += 128;
    float*  wa0  = base_;  base_ += 128;
    float*  wa1  = base_;  base_ += 128;
    float*  bes  = base_;  base_ += 128;

    float2* part  = (float2*)partF;
    float*  dual  = partF;
    float*  dualB = partF + 2048;
    float*  fos   = partF;

    __shared__ float s_lk[4], s_a0[4], s_a1[4];
    __shared__ int   s_flagok[3], s_allok;
    __shared__ unsigned s_bal[4], s_balc[4];

    const int i    = blockIdx.x;
    const int tid  = threadIdx.x;
    const int w    = tid >> 5;
    const int lane = tid & 31;
    const int kslab = w >> 1, jh = w & 1;
    const int j0 = jh*64 + lane*2;
    const int jg = tid & 63, ks = tid >> 6;

    // ---- staging: constants, W2->smem, W1_top->regs ----
    if (tid < H1D) b1s[tid] = b1[tid];
    if (tid < H2D){ b2s[tid]=b2[tid]; wlks[tid]=wlk[tid];
                    wa0[tid]=wact[2*tid]; wa1[tid]=wact[2*tid+1]; }
    if (tid < EE){ bes[tid] = be[tid]; selP[tid] = 0.f; }
    const float blkv = __ldg(blk), ba0v = __ldg(bact), ba1v = __ldg(bact+1);

    #pragma unroll
    for (int q = 0; q < 16; q++)
        ((float4*)W2s)[q*TPB + tid] = ((const float4*)W2)[q*TPB + tid];

    ull w1p[32];
    #pragma unroll
    for (int kk = 0; kk < 16; kk++){
        ulonglong2 t = *(const ulonglong2*)(W1 + (ks*16+kk)*H1D + jg*4);
        w1p[2*kk] = t.x; w1p[2*kk+1] = t.y;
    }

    // ---- fused init phase A ----
    fos[tid] = fo[i*FIN + tid];
    if (tid < 128){
        int e = tid;
        unsigned b  = __ballot_sync(0xffffffffu, adj[i*NN + e] != 0.0f);
        unsigned bc = __ballot_sync(0xffffffffu, (adj[e*NN + i] != 0.0f) || (e == i));
        if ((e & 31) == 0){ s_bal[e >> 5] = b; s_balc[e >> 5] = bc; }
    }
    __syncthreads();

    const ull tLi = (ull)s_balc[0] | ((ull)s_balc[1] << 32);
    const ull tHi = (ull)s_balc[2] | ((ull)s_balc[3] << 32);
    int cc = 0; int candv[3] = {-1,-1,-1};
    {
        int c = 0;
        #pragma unroll
        for (int wq = 0; wq < 4; wq++){
            unsigned bb = s_bal[wq];
            while (bb){
                int bit = __ffs(bb) - 1; bb &= bb - 1;
                int vtx = wq*32 + bit;
                if (c < 3) candv[c] = vtx;
                c++;
            }
        }
        cc = (c > 3) ? 3 : c;
    }
    int needany;
    {
        ull aL, aH;
        if (i < 63)       { aL = tLi & ~((2ull << i) - 1ull); aH = tHi; }
        else if (i == 63) { aL = 0ull; aH = tHi; }
        else if (i < 127) { aL = 0ull; aH = tHi & ~((2ull << (i-64)) - 1ull); }
        else              { aL = 0ull; aH = 0ull; }
        needany = ((aL | aH) != 0ull);
    }
    ull mskL, mskH;
    if (i < 64){ mskL = (1ull << i) - 1ull; mskH = 0ull; }
    else       { mskL = ~0ull; mskH = (1ull << (i - 64)) - 1ull; }
    const int expI = __popcll(tLi & mskL) + __popcll(tHi & mskH);
    const int totI = __popcll(tLi) + __popcll(tHi);
    int selfInCand = 0;
    #pragma unroll
    for (int q = 0; q < 3; q++) if (q < cc && candv[q] == i) selfInCand = 1;

    if (tid < 128){
        int e = tid;
        float s = 0.f;
        #pragma unroll 16
        for (int f = 0; f < FIN; f++) s += fos[f] * We[f*EE + e];
        g_P[i*EE + e] = s;
        Pis[e] = s;
        float f0 = fmaxf(s + bes[e], 0.f);
        g_feat0[i*EE + e] = f0;
        curx[e] = f0;
    }
    __syncthreads();

    if (tid < H1D){
        int j = tid;
        float st = 0.f, sb = 0.f;
        #pragma unroll 16
        for (int k = 0; k < EE; k++){
            float f = curx[k];
            st += f * W1[k*H1D + j];
            sb += f * W1[(EE+k)*H1D + j];
        }
        a_[j] = st; a0s[j] = st;
        g_G0[i*H1D + j] = sb;
        g_G [i*H1D + j] = sb;
    }
    if (tid == 0){ g_touchL[i] = tLi; g_touchH[i] = tHi; }
    __syncthreads();
    if (tid == 0) red_release_add1(&g_init[i]);

    // ---- phase B: wait candidates' init, prefetch their static rows ----
    if (cc > 0){
        if (w == 0){
            int r = (lane < cc) ? candv[lane] : -1;
            int pend = (r >= 0);
            while (__ballot_sync(0xffffffffu, pend)){
                if (pend && ld_acquire(&g_init[r]) >= 1) pend = 0;
            }
        }
        __syncthreads();
    } else {
        __syncthreads();
    }

    for (int t = tid; t < 768; t += TPB){
        int q = t >> 8, k = t & 255;
        if (q < cc){ float g = g_G0[candv[q]*H1D + k]; G0s[t] = g; Grow[t] = g; }
    }
    if (tid < 384){
        int q = tid >> 7, e = tid & 127;
        if (q < cc){ Pvs[q*128+e] = g_P[candv[q]*EE+e];
                     f0vs[q*128+e] = g_feat0[candv[q]*EE+e]; }
    }
    __syncthreads();

    // =================== SPECULATIVE FULL-NODE ROLLOUT ===================
    int aliveM = (1 << cc) - 1, na = cc;
    int gdirty = 0, needgi = 0, qi = -1;
    int nsel = 0, selmask = 0, rowi_g0 = 1;
    int recQ0 = -1, recQ1 = -1, recQ2 = -1;
    int recV0 = -1, recV1 = -1, recV2 = -1;
    float cntf = 0.f;

    if (cc > 0)
    for (int step = 0; step < 3; step++){
        if (na == 0) break;

        int slots[4]; int ns = 0;
        #pragma unroll
        for (int q = 0; q < 3; q++) if ((aliveM >> q) & 1) slots[ns++] = q;
        slots[ns++] = -1;
        int npair = (ns + 1) >> 1;

        // S1
        {
            int k = tid & 255, hi = tid >> 8;
            float ak = a_[k] + b1s[k];
            #pragma unroll
            for (int h = 0; h < 2; h++){
                int s = hi*2 + h; float val = 0.f;
                if (s < ns){
                    int q = slots[s];
                    if (q < 0) val = fmaxf(ak, 0.f);
                    else {
                        int v = candv[q];
                        float gg = (v > 0) ? Grow[q*256 + k] : 0.f;   // `if v>0` quirk
                        val = fmaxf(ak + gg, 0.f);
                    }
                }
                h1T[k*4 + s] = val;
            }
        }
        __syncthreads();
        if (npair == 2) s2_compute<2>(h1T, W2s, part, kslab, j0);
        else            s2_compute<1>(h1T, W2s, part, kslab, j0);
        __syncthreads();
        if (w < ns){
            int pair = w >> 1, el = w & 1;
            float lk = 0.f, p0 = 0.f, p1 = 0.f;
            #pragma unroll
            for (int qq = 0; qq < 4; qq++){
                int j = lane + qq*32;
                float ssm = b2s[j];
                #pragma unroll
                for (int kq = 0; kq < 8; kq++){
                    float2 vv = part[(pair*8 + kq)*H2D + j];
                    ssm += el ? vv.y : vv.x;
                }
                float h = fmaxf(ssm, 0.f);
                lk += h*wlks[j]; p0 += h*wa0[j]; p1 += h*wa1[j];
            }
            #pragma unroll
            for (int off = 16; off; off >>= 1){
                lk += __shfl_xor_sync(0xffffffffu, lk, off);
                p0 += __shfl_xor_sync(0xffffffffu, p0, off);
                p1 += __shfl_xor_sync(0xffffffffu, p1, off);
            }
            if (lane == 0){ s_lk[w]=lk+blkv; s_a0[w]=p0+ba0v; s_a1[w]=p1+ba1v; }
        }
        __syncthreads();

        float best = -3.4028235e38f; int bs = -1;
        for (int s = 0; s < ns-1; s++){
            float l = s_lk[s];
            if (l > best){ best = l; bs = s; }
        }
        if (s_lk[ns-1] > best) break;           // sentinel

        int qsel = -1;
        #pragma unroll
        for (int s = 0; s < 3; s++) if (s == bs) qsel = slots[s];
        int vsel = candv[qsel];
        int at = (s_a1[bs] > s_a0[bs]) ? 1 : 0;
        float denom = cntf + (float)at + 1.0f;
        cntf += (float)at;
        aliveM &= ~(1 << qsel); na--;
        if (nsel == 0){ recQ0 = qsel; recV0 = vsel; }
        else if (nsel == 1){ recQ1 = qsel; recV1 = vsel; }
        else { recQ2 = qsel; recV2 = vsel; }
        nsel++; selmask |= 1 << qsel;
        needgi = 0; qi = -1;
        #pragma unroll
        for (int q = 0; q < 3; q++)
            if (((aliveM >> q) & 1) && candv[q] == i){ needgi = 1; qi = q; }
        gdirty = (vsel == i) ? 0 : 1;
        if (vsel == i) rowi_g0 = 1;

        // local S4b (no global writes)
        if (tid < 128){
            int e = tid;
            float pv = Pvs[qsel*128+e], pi = Pis[e];
            float nx = fmaxf((selP[e] + (float)at*pv + pi)/denom + bes[e], 0.f);
            float f0v = f0vs[qsel*128+e];
            float fx = (vsel == i) ? f0v : nx;
            if (at) selP[e] += pv;
            curx[e] = fx;
        }
        __syncthreads();
        if (na == 0) break;
        if (step >= 2) break;

        // S5 (local): a_ update + self-row bottom if needgi
        {
            ull acc0 = 0, acc1 = 0;
            #pragma unroll
            for (int kk = 0; kk < 16; kk++){
                ull cp = packff(curx[ks*16 + kk]);
                acc0 = ffma2(w1p[2*kk],   cp, acc0);
                acc1 = ffma2(w1p[2*kk+1], cp, acc1);
            }
            ulonglong2 sb2; sb2.x = 0ull; sb2.y = 0ull;
            if (needgi){
                const float* bwB = W1 + (EE + ks*16)*H1D + jg*4;
                ull b0 = 0, b1u = 0;
                #pragma unroll
                for (int kk = 0; kk < 16; kk++){
                    ulonglong2 wrb = *(const ulonglong2*)(bwB + kk*H1D);
                    ull cp = packff(curx[ks*16 + kk]);
                    b0  = ffma2(wrb.x, cp, b0);
                    b1u = ffma2(wrb.y, cp, b1u);
                }
                sb2.x = b0; sb2.y = b1u;
            }
            ulonglong2 st2; st2.x = acc0; st2.y = acc1;
            *(ulonglong2*)(dual + ks*H1D + jg*4) = st2;
            if (needgi) *(ulonglong2*)(dualB + ks*H1D + jg*4) = sb2;
        }
        __syncthreads();
        if (tid < H1D){
            float ssum = 0.f;
            #pragma unroll
            for (int kq = 0; kq < 8; kq++) ssum += dual[kq*H1D + tid];
            a_[tid] = ssum;
        } else if (needgi){
            int jj = tid - 256;
            float sb = 0.f;
            #pragma unroll
            for (int kq = 0; kq < 8; kq++) sb += dualB[kq*H1D + jj];
            Grow[qi*256 + jj] = sb;
            Gis[jj] = sb;
        }
        if (needgi){ gdirty = 0; rowi_g0 = 0; }
        __syncthreads();
    } // spec steps

    // spec flush math (custom final G[i]) if needed
    if (gdirty && needany){
        {
            const float* bwB = W1 + (EE + ks*16)*H1D + jg*4;
            ull b0 = 0, b1u = 0;
            #pragma unroll
            for (int kk = 0; kk < 16; kk++){
                ulonglong2 wrb = *(const ulonglong2*)(bwB + kk*H1D);
                ull cp = packff(curx[ks*16 + kk]);
                b0  = ffma2(wrb.x, cp, b0);
                b1u = ffma2(wrb.y, cp, b1u);
            }
            ulonglong2 st2; st2.x = b0; st2.y = b1u;
            *(ulonglong2*)(dual + ks*H1D + jg*4) = st2;
        }
        __syncthreads();
        if (tid < H1D){
            float ssum = 0.f;
            #pragma unroll
            for (int kq = 0; kq < 8; kq++) ssum += dual[kq*H1D + tid];
            Gis[tid] = ssum;
        }
        rowi_g0 = 0;
        __syncthreads();
    }

    // =================== WAIT + FLAGS ===================
    if (cc > 0){
        if (w == 0){
            int r = -1, ex = 0;
            if (lane < cc){
                r = candv[lane];
                ex = __popcll(g_touchL[r] & mskL) + __popcll(g_touchH[r] & mskH);
            }
            int pend = (r >= 0);
            while (__ballot_sync(0xffffffffu, pend)){
                if (pend && ld_acquire(&g_rowcnt[r]) >= ex) pend = 0;
            }
            int ok = 1;
            if (lane < cc){
                int v = candv[lane];
                ok = (v <= 0) ? 1 : ld_acquire(&g_isG0[v]);
                s_flagok[lane] = ok;
            }
            int all = __all_sync(0xffffffffu, ok);
            if (lane == 0) s_allok = all;
        }
        __syncthreads();
    } else {
        if (tid == 0) s_allok = 1;
        __syncthreads();
    }

    if (s_allok){
        // =================== SPEC HIT: replay side effects ===================
        if (nsel > 0){
            if (!selfInCand){
                if (w == 0){ while (ld_acquire(&g_rowcnt[i]) < expI) { } }
            }
            __syncthreads();
            if (tid == 0){
                g_upd[i] = 1;
                if (recV0 >= 0) g_upd[recV0] = 1;
                if (recV1 >= 0) g_upd[recV1] = 1;
                if (recV2 >= 0) g_upd[recV2] = 1;
                if (recV0 >= 0 && recV0 != i) g_isG0[recV0] = 1;
                if (recV1 >= 0 && recV1 != i) g_isG0[recV1] = 1;
                if (recV2 >= 0 && recV2 != i) g_isG0[recV2] = 1;
                g_isG0[i] = rowi_g0;
            }
            #pragma unroll
            for (int s = 0; s < 3; s++){
                int v = (s==0) ? recV0 : (s==1) ? recV1 : recV2;
                int q = (s==0) ? recQ0 : (s==1) ? recQ1 : recQ2;
                if (s < nsel && v != i){
                    if (tid < 128) g_feat[v*EE + tid] = f0vs[q*128 + tid];
                    else if (tid < 384) g_G[v*H1D + (tid-128)] = G0s[q*256 + (tid-128)];
                }
            }
            if (tid < 128) g_feat[i*EE + tid] = curx[tid];
            if (rowi_g0 == 0 && tid >= 128 && tid < 384)
                g_G[i*H1D + (tid-128)] = Gis[tid-128];
            __syncthreads();
            if (tid == 0){
                if (recV0 >= 0 && recV0 != i) red_release_add1(&g_rowcnt[recV0]);
                if (recV1 >= 0 && recV1 != i) red_release_add1(&g_rowcnt[recV1]);
                if (recV2 >= 0 && recV2 != i) red_release_add1(&g_rowcnt[recV2]);
            }
        }
        __syncthreads();
        if (tid == 0){
            #pragma unroll
            for (int q = 0; q < 3; q++)
                if (q < cc && !((selmask >> q) & 1) && candv[q] != i)
                    red_release_add1(&g_rowcnt[candv[q]]);
            red_release_add1(&g_rowcnt[i]);
        }
    } else {
        // =================== SPEC MISS: rebuild and re-run live ===============
        for (int t = tid; t < 768; t += TPB){
            int q = t >> 8, k = t & 255;
            if (q < cc){
                int v = candv[q];
                float g = 0.f;
                if (v > 0) g = s_flagok[q] ? G0s[t] : g_G[v*H1D + k];
                Grow[t] = g;
            }
        }
        if (tid < H1D) a_[tid] = a0s[tid];
        if (tid < 128) selP[tid] = 0.f;
        __syncthreads();

        aliveM = (1 << cc) - 1; na = cc;
        int done = 0; gdirty = 0; needgi = 0; qi = -1;
        int pub = 0, rowiOK = selfInCand;
        rowi_g0 = 1; cntf = 0.f;

        for (int step = 0; step < 3; step++){
            if (na == 0) break;

            int slots[4]; int ns = 0;
            #pragma unroll
            for (int q = 0; q < 3; q++) if ((aliveM >> q) & 1) slots[ns++] = q;
            slots[ns++] = -1;
            int npair = (ns + 1) >> 1;

            // S1
            {
                int k = tid & 255, hi = tid >> 8;
                float ak = a_[k] + b1s[k];
                #pragma unroll
                for (int h = 0; h < 2; h++){
                    int s = hi*2 + h; float val = 0.f;
                    if (s < ns){
                        int q = slots[s];
                        if (q < 0) val = fmaxf(ak, 0.f);
                        else {
                            int v = candv[q];
                            float gg = (v > 0) ? Grow[q*256 + k] : 0.f;
                            val = fmaxf(ak + gg, 0.f);
                        }
                    }
                    h1T[k*4 + s] = val;
                }
            }
            __syncthreads();
            if (npair == 2) s2_compute<2>(h1T, W2s, part, kslab, j0);
            else            s2_compute<1>(h1T, W2s, part, kslab, j0);
            __syncthreads();
            if (w < ns){
                int pair = w >> 1, el = w & 1;
                float lk = 0.f, p0 = 0.f, p1 = 0.f;
                #pragma unroll
                for (int qq = 0; qq < 4; qq++){
                    int j = lane + qq*32;
                    float ssm = b2s[j];
                    #pragma unroll
                    for (int kq = 0; kq < 8; kq++){
                        float2 vv = part[(pair*8 + kq)*H2D + j];
                        ssm += el ? vv.y : vv.x;
                    }
                    float h = fmaxf(ssm, 0.f);
                    lk += h*wlks[j]; p0 += h*wa0[j]; p1 += h*wa1[j];
                }
                #pragma unroll
                for (int off = 16; off; off >>= 1){
                    lk += __shfl_xor_sync(0xffffffffu, lk, off);
                    p0 += __shfl_xor_sync(0xffffffffu, p0, off);
                    p1 += __shfl_xor_sync(0xffffffffu, p1, off);
                }
                if (lane == 0){ s_lk[w]=lk+blkv; s_a0[w]=p0+ba0v; s_a1[w]=p1+ba1v; }
            }
            __syncthreads();

            float best = -3.4028235e38f; int bs = -1;
            for (int s = 0; s < ns-1; s++){
                float l = s_lk[s];
                if (l > best){ best = l; bs = s; }
            }
            int vsel = 0, at = 0, qsel = -1, sel = 0; float denom = 1.f;
            if (s_lk[ns-1] > best){
                done = 1;
            } else {
                #pragma unroll
                for (int s = 0; s < 3; s++) if (s == bs) qsel = slots[s];
                vsel = candv[qsel];
                at = (s_a1[bs] > s_a0[bs]) ? 1 : 0;
                denom = cntf + (float)at + 1.0f;
                cntf += (float)at;
                aliveM &= ~(1 << qsel); na--; sel = 1;
                needgi = 0; qi = -1;
                #pragma unroll
                for (int q = 0; q < 3; q++)
                    if (((aliveM >> q) & 1) && candv[q] == i){ needgi = 1; qi = q; }
                gdirty = (vsel == i) ? 0 : 1;
            }
            if (done) break;

            if (sel && !rowiOK){
                if (w == 0){ while (ld_acquire(&g_rowcnt[i]) < expI) { } }
                __syncthreads();
                rowiOK = 1;
            }

            // S4b with writes
            {
                if (tid == 0){
                    g_upd[i] = 1; g_upd[vsel] = 1;
                    if (vsel != i) g_isG0[vsel] = 1;
                }
                int grp = tid >> 7, e = tid & 127;
                if (grp == 0){
                    float pv = Pvs[qsel*128+e], pi = Pis[e];
                    float nx = fmaxf((selP[e] + (float)at*pv + pi)/denom + bes[e], 0.f);
                    float f0v = f0vs[qsel*128+e];
                    float fx = (vsel == i) ? f0v : nx;
                    if (at) selP[e] += pv;
                    g_feat[i*EE + e] = fx;
                    curx[e] = fx;
                } else if (grp == 1){
                    g_feat[vsel*EE + e] = f0vs[qsel*128+e];
                } else {
                    int jj = tid - 256;
                    g_G[vsel*H1D + jj] = G0s[qsel*256 + jj];
                }
            }
            __syncthreads();
            if (tid == 0 && vsel != i) red_release_add1(&g_rowcnt[vsel]);
            if (vsel != i) pub |= 1 << qsel; else rowi_g0 = 1;

            if (na == 0) break;
            if (step >= 2) break;

            // S5
            {
                ull acc0 = 0, acc1 = 0;
                #pragma unroll
                for (int kk = 0; kk < 16; kk++){
                    ull cp = packff(curx[ks*16 + kk]);
                    acc0 = ffma2(w1p[2*kk],   cp, acc0);
                    acc1 = ffma2(w1p[2*kk+1], cp, acc1);
                }
                ulonglong2 sb2; sb2.x = 0ull; sb2.y = 0ull;
                if (needgi){
                    const float* bwB = W1 + (EE + ks*16)*H1D + jg*4;
                    ull b0 = 0, b1u = 0;
                    #pragma unroll
                    for (int kk = 0; kk < 16; kk++){
                        ulonglong2 wrb = *(const ulonglong2*)(bwB + kk*H1D);
                        ull cp = packff(curx[ks*16 + kk]);
                        b0  = ffma2(wrb.x, cp, b0);
                        b1u = ffma2(wrb.y, cp, b1u);
                    }
                    sb2.x = b0; sb2.y = b1u;
                }
                ulonglong2 st2; st2.x = acc0; st2.y = acc1;
                *(ulonglong2*)(dual + ks*H1D + jg*4) = st2;
                if (needgi) *(ulonglong2*)(dualB + ks*H1D + jg*4) = sb2;
            }
            __syncthreads();
            if (tid < H1D){
                float ssum = 0.f;
                #pragma unroll
                for (int kq = 0; kq < 8; kq++) ssum += dual[kq*H1D + tid];
                a_[tid] = ssum;
            } else if (needgi){
                int jj = tid - 256;
                float sb = 0.f;
                #pragma unroll
                for (int kq = 0; kq < 8; kq++) sb += dualB[kq*H1D + jj];
                g_G[i*H1D + jj] = sb;
                Grow[qi*256 + jj] = sb;
            }
            if (needgi){ gdirty = 0; rowi_g0 = 0; }
            __syncthreads();
        } // live steps

        __syncthreads();
        if (tid == 0){
            #pragma unroll
            for (int q = 0; q < 3; q++)
                if (q < cc && !((pub >> q) & 1) && candv[q] != i)
                    red_release_add1(&g_rowcnt[candv[q]]);
        }

        if (gdirty && needany){
            {
                const float* bwB = W1 + (EE + ks*16)*H1D + jg*4;
                ull b0 = 0, b1u = 0;
                #pragma unroll
                for (int kk = 0; kk < 16; kk++){
                    ulonglong2 wrb = *(const ulonglong2*)(bwB + kk*H1D);
                    ull cp = packff(curx[ks*16 + kk]);
                    b0  = ffma2(wrb.x, cp, b0);
                    b1u = ffma2(wrb.y, cp, b1u);
                }
                ulonglong2 st2; st2.x = b0; st2.y = b1u;
                *(ulonglong2*)(dual + ks*H1D + jg*4) = st2;
            }
            __syncthreads();
            if (tid < H1D){
                float ssum = 0.f;
                #pragma unroll
                for (int kq = 0; kq < 8; kq++) ssum += dual[kq*H1D + tid];
                g_G[i*H1D + tid] = ssum;
            }
            rowi_g0 = 0;
        }
        __syncthreads();
        if (tid == 0){
            g_isG0[i] = rowi_g0;
            red_release_add1(&g_rowcnt[i]);
        }
    }

    // ---- out phase ----
    if (w == 0){
        while (ld_acquire(&g_rowcnt[i]) < totI) { }
    }
    __syncthreads();
    if (tid < EE){
        int u  = __ldcg(&g_upd[i]);
        float f = __ldcg(&g_feat[i*EE + tid]);
        out[i*EE + tid] = u ? f : 0.f;
    }
}

// ---------------- launch ------------------------------------------------------
static const int DYN_SMEM = (32768 + 1024 + 4096 + 768 + 768 + 384 + 384
                             + 128 + 256 + 256 + 256 + 128 + 128 + 256 + 128
                             + 128 + 128 + 128 + 128) * (int)sizeof(float);

extern "C" void kernel_launch(void* const* d_in, const int* in_sizes, int n_in,
                              void* d_out, int out_size)
{
    const float* adj = (const float*)d_in[0];
    const float* fo  = (const float*)d_in[1];
    // d_in[2] = labels (unused)
    const float* We  = (const float*)d_in[3];
    const float* be  = (const float*)d_in[4];
    const float* W1  = (const float*)d_in[5];
    const float* b1  = (const float*)d_in[6];
    const float* W2  = (const float*)d_in[7];
    const float* b2  = (const float*)d_in[8];
    const float* wlk = (const float*)d_in[9];
    const float* blk = (const float*)d_in[10];
    const float* wac = (const float*)d_in[11];
    const float* bac = (const float*)d_in[12];
    float* out = (float*)d_out;

    cudaFuncSetAttribute(dataflow_kernel, cudaFuncAttributeMaxDynamicSharedMemorySize, DYN_SMEM);

    zero_kernel<<<1, 128>>>();
    dataflow_kernel<<<NN, TPB, DYN_SMEM>>>(adj, fo, We, be, W1, W2,
                                           b1, b2, wlk, blk, wac, bac, out);
}